// round 15
// baseline (speedup 1.0000x reference)
#include <cuda_runtime.h>
#include <cuda_bf16.h>
#include <cuda_fp16.h>
#include <cstdint>

// ---------------------------------------------------------------------------
// DeformableAttention (B=8, N=4096, C=256, S=4, NH=8, NL=1, NP=4, HD=32)
//
// fp16 mma.sync pipeline v6 (3 launches):
//   1. prep: vmean->fp16; Wv,Wo transposes; weight fold (4-way split +
//      shuffle reduce); bias fold (warp-parallel)
//   2. vpm   = vmean @ Wv + bv            (BN=64 GEMM, fp16 out)
//   3. mega (BM=32, 1024 blocks): q fp32 -> smem fp16 -> offattn GEMM ->
//      softmax + bilinear sampling -> out GEMM -> out
// ---------------------------------------------------------------------------

namespace {
constexpr int Bn   = 8;
constexpr int Nn   = 4096;
constexpr int Cc   = 256;   // K for all GEMMs
constexpr int NHh  = 8;
constexpr int NPp  = 4;
constexpr int HDd  = 32;
constexpr int ROWS = Bn * Nn;    // 32768
constexpr int GW   = 64;
constexpr int NF   = 128;        // padded offattn width
}

// -------------------- scratch (static device globals) ----------------------
__device__ __align__(16) __half g_vm16[Nn * Cc];
__device__ __align__(16) __half g_vpm_h[Nn * Cc];
__device__ __align__(16) float g_bfold[NF];
__device__ __align__(16) __half g_WvT[Cc * Cc];
__device__ __align__(16) __half g_WoT[Cc * Cc];
__device__ __align__(16) __half g_WfT[NF * Cc];

// -------------------- helpers ----------------------------------------------
__device__ __forceinline__ void mma_f16(float c[4], const uint32_t a[4],
                                        const uint32_t b[2]) {
    asm volatile(
        "mma.sync.aligned.m16n8k16.row.col.f32.f16.f16.f32 "
        "{%0,%1,%2,%3}, {%4,%5,%6,%7}, {%8,%9}, {%0,%1,%2,%3};\n"
        : "+f"(c[0]), "+f"(c[1]), "+f"(c[2]), "+f"(c[3])
        : "r"(a[0]), "r"(a[1]), "r"(a[2]), "r"(a[3]), "r"(b[0]), "r"(b[1]));
}

__device__ __forceinline__ void ldmx4(uint32_t r[4], uint32_t addr) {
    asm volatile(
        "ldmatrix.sync.aligned.m8n8.x4.shared.b16 {%0,%1,%2,%3}, [%4];\n"
        : "=r"(r[0]), "=r"(r[1]), "=r"(r[2]), "=r"(r[3]) : "r"(addr));
}

__device__ __forceinline__ void cp_async16(uint32_t dst, const void* src) {
    asm volatile("cp.async.cg.shared.global [%0], [%1], 16;\n"
                 :: "r"(dst), "l"(src));
}
__device__ __forceinline__ void cp_commit() {
    asm volatile("cp.async.commit_group;\n");
}
template <int NN>
__device__ __forceinline__ void cp_wait() {
    asm volatile("cp.async.wait_group %0;\n" :: "n"(NN));
}

// -------------------- GEMM: C = A @ Bt^T + bias (vpm only) -----------------
template <bool HALF_OUT>
__global__ void __launch_bounds__(256, 2)
gemm_f16(const __half* __restrict__ Ag,
         const __half* __restrict__ Bg,
         const float* __restrict__ bias, void* __restrict__ Cout,
         int M, int N) {
    constexpr int K = Cc, BM = 128, BN = 64, BK = 32;
    constexpr int NK = K / BK;     // 8
    constexpr int STB = 12288;
    __shared__ __align__(128) uint8_t smem[3 * STB];
    const uint32_t sb = (uint32_t)__cvta_generic_to_shared(smem);

    const int t = threadIdx.x, w = t >> 5, l = t & 31;
    const int wm = w & 3, wn = w >> 2;
    const int g = l >> 2, qq = l & 3;
    const int blockRow = blockIdx.y * BM;
    const int blockCol = blockIdx.x * BN;
    const int lr = t >> 2, lc = t & 3;

    float acc[2][4][4];
#pragma unroll
    for (int i = 0; i < 2; i++)
#pragma unroll
        for (int j = 0; j < 4; j++)
#pragma unroll
            for (int x = 0; x < 4; x++) acc[i][j][x] = 0.f;

    auto stage = [&](int buf, int k0) {
        const uint32_t base = sb + buf * STB;
#pragma unroll
        for (int j = 0; j < 2; j++) {
            int row = lr + j * 64;
            uint32_t sw = (uint32_t)row * 64 + (uint32_t)((lc ^ ((row >> 1) & 3)) * 16);
            cp_async16(base + sw, Ag + (size_t)(blockRow + row) * K + k0 + lc * 8);
        }
        {
            uint32_t sw = (uint32_t)lr * 64 + (uint32_t)((lc ^ ((lr >> 1) & 3)) * 16);
            cp_async16(base + 8192 + sw, Bg + (size_t)(blockCol + lr) * K + k0 + lc * 8);
        }
        cp_commit();
    };

    auto compute = [&](int buf) {
        const uint32_t base = sb + buf * STB;
        const int seg = l >> 3, sl = l & 7;
#pragma unroll
        for (int ks = 0; ks < 2; ks++) {
            uint32_t bF[4][2];
#pragma unroll
            for (int nt = 0; nt < 2; nt++) {
                int r = wn * 32 + nt * 16 + (seg >> 1) * 8 + sl;
                int c = ks * 2 + (seg & 1);
                uint32_t addr = (uint32_t)r * 64 + (uint32_t)((c ^ ((r >> 1) & 3)) * 16);
                uint32_t tmp[4];
                ldmx4(tmp, base + 8192 + addr);
                bF[nt * 2][0] = tmp[0]; bF[nt * 2][1] = tmp[1];
                bF[nt * 2 + 1][0] = tmp[2]; bF[nt * 2 + 1][1] = tmp[3];
            }
            uint32_t aF[2][4];
#pragma unroll
            for (int mt = 0; mt < 2; mt++) {
                int r = wm * 32 + mt * 16 + (seg & 1) * 8 + sl;
                int c = ks * 2 + (seg >> 1);
                uint32_t addr = (uint32_t)r * 64 + (uint32_t)((c ^ ((r >> 1) & 3)) * 16);
                ldmx4(aF[mt], base + addr);
            }
#pragma unroll
            for (int mt = 0; mt < 2; mt++)
#pragma unroll
                for (int nf = 0; nf < 4; nf++)
                    mma_f16(acc[mt][nf], aF[mt], bF[nf]);
        }
    };

    stage(0, 0);
    stage(1, BK);
    for (int kt = 0; kt < NK; kt++) {
        if (kt + 2 < NK) cp_wait<1>();
        else             cp_wait<0>();
        __syncthreads();
        if (kt + 2 < NK) stage((kt + 2) % 3, (kt + 2) * BK);
        compute(kt % 3);
    }

#pragma unroll
    for (int mt = 0; mt < 2; mt++) {
        int row = blockRow + wm * 32 + mt * 16 + g;
#pragma unroll
        for (int nf = 0; nf < 4; nf++) {
            int col = blockCol + wn * 32 + nf * 8 + 2 * qq;
            float2 bb = *(const float2*)&bias[col];
            float v00 = acc[mt][nf][0] + bb.x, v01 = acc[mt][nf][1] + bb.y;
            float v10 = acc[mt][nf][2] + bb.x, v11 = acc[mt][nf][3] + bb.y;
            if (HALF_OUT) {
                __half2* Ch = (__half2*)Cout;
                Ch[((size_t)row * N + col) >> 1]       = __floats2half2_rn(v00, v01);
                Ch[((size_t)(row + 8) * N + col) >> 1] = __floats2half2_rn(v10, v11);
            } else {
                float* Cf = (float*)Cout;
                *(float2*)&Cf[(size_t)row * N + col]       = make_float2(v00, v01);
                *(float2*)&Cf[(size_t)(row + 8) * N + col] = make_float2(v10, v11);
            }
        }
    }
}

// -------------------- mega: q convert + offattn GEMM + sampling + out GEMM -
// (identical to R14 passing version)
__global__ void __launch_bounds__(256, 2)
mega_kernel(const float* __restrict__ qg,
            const __half* __restrict__ Bf,
            const float* __restrict__ bfold,
            const __half* __restrict__ WoT,
            const float* __restrict__ bo,
            float* __restrict__ out) {
    constexpr int K = Cc, BK = 32, NK = 8;
    constexpr uint32_t PRE = 0, SOA = 16384;
    constexpr uint32_t ASTG = 16384, ASTG_SZ = 8192;
    constexpr uint32_t CS0 = 32768, CS1 = 16384;
    __shared__ __align__(128) uint8_t smem[49152];
    const uint32_t sb = (uint32_t)__cvta_generic_to_shared(smem);
    float* s_oa = (float*)(smem + SOA);

    const int t = threadIdx.x, w = t >> 5, l = t & 31;
    const int wm = w & 1, wn = w >> 1;
    const int g = l >> 2, qq = l & 3;
    const int seg = l >> 3, sl = l & 7;
    const int blockRow = blockIdx.x * 32;

    // q preload: 32x256 fp32 -> fp16 into PRE (swizzled chunks)
    {
        const int row = t >> 3;
        const int g0 = t & 7;
#pragma unroll
        for (int j = 0; j < 4; j++) {
            int grp = g0 + j * 8;
            int col = grp * 8;
            const float* src = qg + (size_t)(blockRow + row) * K + col;
            float4 a = *(const float4*)src;
            float4 b = *(const float4*)(src + 4);
            __half2 h2[4];
            h2[0] = __floats2half2_rn(a.x, a.y);
            h2[1] = __floats2half2_rn(a.z, a.w);
            h2[2] = __floats2half2_rn(b.x, b.y);
            h2[3] = __floats2half2_rn(b.z, b.w);
            int kt = col >> 5;
            int c16 = (col & 31) >> 3;
            uint32_t addr = PRE + (uint32_t)kt * 2048 + (uint32_t)row * 64 +
                            (uint32_t)((c16 ^ ((row >> 1) & 3)) << 4);
            *(uint4*)(smem + addr) = *(const uint4*)h2;
        }
    }

    // Phase A: offattn GEMM (32 x 128)
    {
        float acc[4][4];
#pragma unroll
        for (int j = 0; j < 4; j++)
#pragma unroll
            for (int x = 0; x < 4; x++) acc[j][x] = 0.f;

        auto stageA = [&](int buf, int k0) {
            const uint32_t base = sb + ASTG + buf * ASTG_SZ;
#pragma unroll
            for (int j = 0; j < 2; j++) {
                int ch = t + j * 256;
                int row = ch >> 2, lc = ch & 3;
                uint32_t sw = (uint32_t)row * 64 + (uint32_t)((lc ^ ((row >> 1) & 3)) * 16);
                cp_async16(base + sw, Bf + (size_t)row * K + k0 + lc * 8);
            }
            cp_commit();
        };

        auto computeA = [&](int buf, int kt) {
            const uint32_t base = sb + ASTG + buf * ASTG_SZ;
#pragma unroll
            for (int ks = 0; ks < 2; ks++) {
                uint32_t bF[4][2];
#pragma unroll
                for (int nt = 0; nt < 2; nt++) {
                    int r = wn * 32 + nt * 16 + (seg >> 1) * 8 + sl;
                    int c = ks * 2 + (seg & 1);
                    uint32_t addr = (uint32_t)r * 64 + (uint32_t)((c ^ ((r >> 1) & 3)) * 16);
                    uint32_t tmp[4];
                    ldmx4(tmp, base + addr);
                    bF[nt * 2][0] = tmp[0]; bF[nt * 2][1] = tmp[1];
                    bF[nt * 2 + 1][0] = tmp[2]; bF[nt * 2 + 1][1] = tmp[3];
                }
                uint32_t aF[4];
                int r = wm * 16 + (seg & 1) * 8 + sl;
                int c = ks * 2 + (seg >> 1);
                uint32_t addr = PRE + (uint32_t)kt * 2048 + (uint32_t)r * 64 +
                                (uint32_t)((c ^ ((r >> 1) & 3)) * 16);
                ldmx4(aF, sb + addr);
#pragma unroll
                for (int nf = 0; nf < 4; nf++)
                    mma_f16(acc[nf], aF, bF[nf]);
            }
        };

        stageA(0, 0);
        stageA(1, BK);
        for (int kt = 0; kt < NK; kt++) {
            if (kt + 2 < NK) cp_wait<1>();
            else             cp_wait<0>();
            __syncthreads();
            if (kt + 2 < NK) stageA((kt + 2) % 3, (kt + 2) * BK);
            computeA(kt % 3, kt);
        }
        __syncthreads();

        int rl = wm * 16 + g;
#pragma unroll
        for (int nf = 0; nf < 4; nf++) {
            int col = wn * 32 + nf * 8 + 2 * qq;
            if (col < 96) {
                float b0 = bfold[col], b1 = bfold[col + 1];
                s_oa[rl * 96 + col]           = acc[nf][0] + b0;
                s_oa[rl * 96 + col + 1]       = acc[nf][1] + b1;
                s_oa[(rl + 8) * 96 + col]     = acc[nf][2] + b0;
                s_oa[(rl + 8) * 96 + col + 1] = acc[nf][3] + b1;
            }
        }
        __syncthreads();
    }

    // pre-issue out-GEMM stage 0 — overlaps sampling
    {
#pragma unroll
        for (int j = 0; j < 4; j++) {
            int ch = t + j * 256;
            int row = ch >> 2, lc = ch & 3;
            uint32_t sw = (uint32_t)row * 64 + (uint32_t)((lc ^ ((row >> 1) & 3)) * 16);
            cp_async16(sb + CS0 + sw, WoT + (size_t)row * K + lc * 8);
        }
        cp_commit();
    }

    // Phase B: softmax + bilinear sampling -> PRE
    for (int rl = w * 4; rl < w * 4 + 4; rl++) {
        const int row = blockRow + rl;
        const int n = row & (Nn - 1);
        const float refx = (float)(n & (GW - 1)) * (1.0f / 63.0f);
        const float refy = (float)(n >> 6) * (1.0f / 63.0f);
        const float* oa = s_oa + rl * 96;

#pragma unroll
        for (int h = 0; h < NHh; h++) {
            float l0 = oa[64 + h * 4 + 0];
            float l1 = oa[64 + h * 4 + 1];
            float l2 = oa[64 + h * 4 + 2];
            float l3 = oa[64 + h * 4 + 3];
            float m  = fmaxf(fmaxf(l0, l1), fmaxf(l2, l3));
            float e0 = __expf(l0 - m), e1 = __expf(l1 - m);
            float e2 = __expf(l2 - m), e3 = __expf(l3 - m);
            float inv = 1.0f / (e0 + e1 + e2 + e3);
            float wp[4] = {e0 * inv, e1 * inv, e2 * inv, e3 * inv};

            const __half* fmap = g_vpm_h + h * HDd + l;
            float acc2 = 0.f;
#pragma unroll
            for (int p = 0; p < NPp; p++) {
                float ox = oa[h * 8 + p * 2 + 0];
                float oy = oa[h * 8 + p * 2 + 1];
                float lx = fminf(fmaxf(refx + ox, 0.f), 1.f);
                float ly = fminf(fmaxf(refy + oy, 0.f), 1.f);
                float x = lx * (float)GW - 0.5f;
                float y = ly * (float)GW - 0.5f;
                float xf = floorf(x), yf = floorf(y);
                float tx = x - xf, ty = y - yf;
                int x0 = (int)xf, y0 = (int)yf;
                int x1 = x0 + 1, y1 = y0 + 1;
                bool vx0 = (x0 >= 0), vx1 = (x1 < GW);
                bool vy0 = (y0 >= 0), vy1 = (y1 < GW);
                float w00 = (1.f - tx) * (1.f - ty);
                float w01 = tx * (1.f - ty);
                float w10 = (1.f - tx) * ty;
                float w11 = tx * ty;
                float a = 0.f;
                if (vx0 && vy0) a = fmaf(w00, __half2float(fmap[(size_t)(y0 * GW + x0) * Cc]), a);
                if (vx1 && vy0) a = fmaf(w01, __half2float(fmap[(size_t)(y0 * GW + x1) * Cc]), a);
                if (vx0 && vy1) a = fmaf(w10, __half2float(fmap[(size_t)(y1 * GW + x0) * Cc]), a);
                if (vx1 && vy1) a = fmaf(w11, __half2float(fmap[(size_t)(y1 * GW + x1) * Cc]), a);
                acc2 = fmaf(wp[p], a, acc2);
            }
            uint32_t boff = PRE + (uint32_t)h * 2048 + (uint32_t)rl * 64 +
                            ((((uint32_t)l >> 3) ^ ((uint32_t)(rl >> 1) & 3)) << 4) +
                            ((uint32_t)(l & 7)) * 2;
            *(__half*)(smem + boff) = __float2half_rn(acc2);
        }
    }
    __syncthreads();

    // Phase C: out GEMM (32 x 256) + bo
    {
        float acc[8][4];
#pragma unroll
        for (int j = 0; j < 8; j++)
#pragma unroll
            for (int x = 0; x < 4; x++) acc[j][x] = 0.f;

        auto stageC = [&](int buf, int k0) {
            const uint32_t base = sb + (buf ? CS1 : CS0);
#pragma unroll
            for (int j = 0; j < 4; j++) {
                int ch = t + j * 256;
                int row = ch >> 2, lc = ch & 3;
                uint32_t sw = (uint32_t)row * 64 + (uint32_t)((lc ^ ((row >> 1) & 3)) * 16);
                cp_async16(base + sw, WoT + (size_t)row * K + k0 + lc * 8);
            }
            cp_commit();
        };

        for (int kt = 0; kt < NK; kt++) {
            cp_wait<0>();
            __syncthreads();
            if (kt + 1 < NK) stageC((kt + 1) & 1, (kt + 1) * BK);
            const uint32_t base = sb + ((kt & 1) ? CS1 : CS0);
#pragma unroll
            for (int ks = 0; ks < 2; ks++) {
                uint32_t bF[8][2];
#pragma unroll
                for (int nt = 0; nt < 4; nt++) {
                    int r = wn * 64 + nt * 16 + (seg >> 1) * 8 + sl;
                    int c = ks * 2 + (seg & 1);
                    uint32_t addr = (uint32_t)r * 64 + (uint32_t)((c ^ ((r >> 1) & 3)) * 16);
                    uint32_t tmp[4];
                    ldmx4(tmp, base + addr);
                    bF[nt * 2][0] = tmp[0]; bF[nt * 2][1] = tmp[1];
                    bF[nt * 2 + 1][0] = tmp[2]; bF[nt * 2 + 1][1] = tmp[3];
                }
                uint32_t aF[4];
                int r = wm * 16 + (seg & 1) * 8 + sl;
                int c = ks * 2 + (seg >> 1);
                uint32_t addr = PRE + (uint32_t)kt * 2048 + (uint32_t)r * 64 +
                                (uint32_t)((c ^ ((r >> 1) & 3)) * 16);
                ldmx4(aF, sb + addr);
#pragma unroll
                for (int nf = 0; nf < 8; nf++)
                    mma_f16(acc[nf], aF, bF[nf]);
            }
        }

        int row = blockRow + wm * 16 + g;
#pragma unroll
        for (int nf = 0; nf < 8; nf++) {
            int col = wn * 64 + nf * 8 + 2 * qq;
            float2 bb = *(const float2*)&bo[col];
            *(float2*)&out[(size_t)row * Cc + col] =
                make_float2(acc[nf][0] + bb.x, acc[nf][1] + bb.y);
            *(float2*)&out[(size_t)(row + 8) * Cc + col] =
                make_float2(acc[nf][2] + bb.x, acc[nf][3] + bb.y);
        }
    }
}

// -------------------- prep: vmean, transposes, PARALLEL fold + bias --------
__global__ void prep_kernel(const float* __restrict__ v,
                            const float* __restrict__ Wv,
                            const float* __restrict__ Wo,
                            const float* __restrict__ Wq,
                            const float* __restrict__ bq,
                            const float* __restrict__ Woff,
                            const float* __restrict__ boff,
                            const float* __restrict__ Wattn,
                            const float* __restrict__ battn) {
    const int VT  = Nn * Cc / 4;           // 262144
    const int WT  = Cc * Cc;               // 65536
    const int FT4 = NF * Cc * 4;           // 131072 (fold, 4-way j split)
    const int BT  = NF * 32;               // 4096   (bias, warp per output)
    int idx = blockIdx.x * blockDim.x + threadIdx.x;
    if (idx < VT) {
        const float4* v4 = reinterpret_cast<const float4*>(v);
        float4 a = v4[idx], b = v4[idx + VT], c = v4[idx + 2 * VT], d = v4[idx + 3 * VT];
        __half2 h2[2];
        h2[0] = __floats2half2_rn(0.25f * (a.x + b.x + c.x + d.x),
                                  0.25f * (a.y + b.y + c.y + d.y));
        h2[1] = __floats2half2_rn(0.25f * (a.z + b.z + c.z + d.z),
                                  0.25f * (a.w + b.w + c.w + d.w));
        *(uint2*)&g_vm16[idx * 4] = *(const uint2*)h2;
    } else if (idx < VT + WT) {
        int li = idx - VT;
        int n = li / Cc, k = li % Cc;
        g_WvT[li] = __float2half_rn(Wv[k * Cc + n]);
    } else if (idx < VT + 2 * WT) {
        int li = idx - VT - WT;
        int n = li / Cc, k = li % Cc;
        g_WoT[li] = __float2half_rn(Wo[k * Cc + n]);
    } else if (idx < VT + 2 * WT + FT4) {
        // fold: WfT[c][k] = sum_j Wq[k][j] * Wcat[j][c], 4 lanes per output
        int local = idx - VT - 2 * WT;
        int pair = local >> 2, part = local & 3;
        int k = pair / NF, c = pair % NF;
        float s = 0.f;
        if (c < 96) {
            const float* wq = Wq + k * Cc;
            if (c < 64) {
#pragma unroll 8
                for (int i = 0; i < 64; i++) {
                    int j = part + 4 * i;
                    s = fmaf(wq[j], Woff[j * 64 + c], s);
                }
            } else {
                int cc2 = c - 64;
#pragma unroll 8
                for (int i = 0; i < 64; i++) {
                    int j = part + 4 * i;
                    s = fmaf(wq[j], Wattn[j * 32 + cc2], s);
                }
            }
        }
        s += __shfl_xor_sync(0xffffffffu, s, 1);
        s += __shfl_xor_sync(0xffffffffu, s, 2);
        if (part == 0) g_WfT[c * Cc + k] = __float2half_rn(s);
    } else if (idx < VT + 2 * WT + FT4 + BT) {
        // bias fold: one warp per output element, 8 j's per lane
        int local = idx - VT - 2 * WT - FT4;
        int o = local >> 5, lane = local & 31;
        float s = 0.f;
        if (o < 64) {
#pragma unroll
            for (int i = 0; i < 8; i++) {
                int j = lane + 32 * i;
                s = fmaf(bq[j], Woff[j * 64 + o], s);
            }
        } else if (o < 96) {
            int oo = o - 64;
#pragma unroll
            for (int i = 0; i < 8; i++) {
                int j = lane + 32 * i;
                s = fmaf(bq[j], Wattn[j * 32 + oo], s);
            }
        }
#pragma unroll
        for (int off = 16; off > 0; off >>= 1)
            s += __shfl_xor_sync(0xffffffffu, s, off);
        if (lane == 0) {
            float base = (o < 64) ? boff[o] : (o < 96 ? battn[o - 64] : 0.f);
            g_bfold[o] = (o < 96) ? (base + s) : 0.f;
        }
    }
}

// ---------------------------------------------------------------------------
extern "C" void kernel_launch(void* const* d_in, const int* in_sizes, int n_in,
                              void* d_out, int out_size) {
    (void)in_sizes; (void)n_in; (void)out_size;
    const float* q     = (const float*)d_in[0];
    const float* v     = (const float*)d_in[2];
    const float* Wq    = (const float*)d_in[3];
    const float* bq    = (const float*)d_in[4];
    const float* Wv    = (const float*)d_in[7];
    const float* bv    = (const float*)d_in[8];
    const float* Wo    = (const float*)d_in[9];
    const float* bo    = (const float*)d_in[10];
    const float* Woff  = (const float*)d_in[11];
    const float* boff  = (const float*)d_in[12];
    const float* Wattn = (const float*)d_in[13];
    const float* battn = (const float*)d_in[14];
    float* out = (float*)d_out;

    float* p_bfold;
    __half *p_vm16, *p_vpmh, *p_WvT, *p_WoT, *p_WfT;
    cudaGetSymbolAddress((void**)&p_vm16,  g_vm16);
    cudaGetSymbolAddress((void**)&p_vpmh,  g_vpm_h);
    cudaGetSymbolAddress((void**)&p_bfold, g_bfold);
    cudaGetSymbolAddress((void**)&p_WvT,   g_WvT);
    cudaGetSymbolAddress((void**)&p_WoT,   g_WoT);
    cudaGetSymbolAddress((void**)&p_WfT,   g_WfT);

    // 1. prep (vmean, transposes, parallel weight fold + bias fold)
    {
        int tot = Nn * Cc / 4 + 2 * Cc * Cc + NF * Cc * 4 + NF * 32;
        prep_kernel<<<(tot + 255) / 256, 256>>>(v, Wv, Wo, Wq, bq, Woff,
                                                boff, Wattn, battn);
    }

    // 2. vpm (fp16) = vmean @ Wv + bv
    gemm_f16<true><<<dim3(Cc / 64, Nn / 128), 256>>>(
        p_vm16, p_WvT, bv, p_vpmh, Nn, Cc);

    // 3. mega: q convert + offattn GEMM + sampling + out GEMM
    mega_kernel<<<ROWS / 32, 256>>>(q, p_WfT, p_bfold, p_WoT, bo, out);
}

// round 17
// speedup vs baseline: 1.0335x; 1.0335x over previous
#include <cuda_runtime.h>
#include <cuda_bf16.h>
#include <cuda_fp16.h>
#include <cstdint>

// ---------------------------------------------------------------------------
// DeformableAttention (B=8, N=4096, C=256, S=4, NH=8, NL=1, NP=4, HD=32)
//
// fp16 mma.sync pipeline v7 (3 launches, aux work overlapped with vpm GEMM):
//   1. prep: vmean->fp16; WvT transpose                  (critical for vpm)
//   2. vpm GEMM (grid.y<32) ++ aux blocks (grid.y>=32): WoT transpose,
//      weight fold (4-way split + shuffle), bias fold    (needed by mega)
//   3. mega (BM=32, 1024 blocks): q fp32 -> smem fp16 -> offattn GEMM ->
//      softmax + bilinear sampling -> out GEMM -> out
// ---------------------------------------------------------------------------

namespace {
constexpr int Bn   = 8;
constexpr int Nn   = 4096;
constexpr int Cc   = 256;   // K for all GEMMs
constexpr int NHh  = 8;
constexpr int NPp  = 4;
constexpr int HDd  = 32;
constexpr int ROWS = Bn * Nn;    // 32768
constexpr int GW   = 64;
constexpr int NF   = 128;        // padded offattn width
constexpr int VPM_GY = 32;       // vpm GEMM rows of blocks
}

// -------------------- scratch (static device globals) ----------------------
__device__ __align__(16) __half g_vm16[Nn * Cc];
__device__ __align__(16) __half g_vpm_h[Nn * Cc];
__device__ __align__(16) float g_bfold[NF];
__device__ __align__(16) __half g_WvT[Cc * Cc];
__device__ __align__(16) __half g_WoT[Cc * Cc];
__device__ __align__(16) __half g_WfT[NF * Cc];

// -------------------- helpers ----------------------------------------------
__device__ __forceinline__ void mma_f16(float c[4], const uint32_t a[4],
                                        const uint32_t b[2]) {
    asm volatile(
        "mma.sync.aligned.m16n8k16.row.col.f32.f16.f16.f32 "
        "{%0,%1,%2,%3}, {%4,%5,%6,%7}, {%8,%9}, {%0,%1,%2,%3};\n"
        : "+f"(c[0]), "+f"(c[1]), "+f"(c[2]), "+f"(c[3])
        : "r"(a[0]), "r"(a[1]), "r"(a[2]), "r"(a[3]), "r"(b[0]), "r"(b[1]));
}

__device__ __forceinline__ void ldmx4(uint32_t r[4], uint32_t addr) {
    asm volatile(
        "ldmatrix.sync.aligned.m8n8.x4.shared.b16 {%0,%1,%2,%3}, [%4];\n"
        : "=r"(r[0]), "=r"(r[1]), "=r"(r[2]), "=r"(r[3]) : "r"(addr));
}

__device__ __forceinline__ void cp_async16(uint32_t dst, const void* src) {
    asm volatile("cp.async.cg.shared.global [%0], [%1], 16;\n"
                 :: "r"(dst), "l"(src));
}
__device__ __forceinline__ void cp_commit() {
    asm volatile("cp.async.commit_group;\n");
}
template <int NN>
__device__ __forceinline__ void cp_wait() {
    asm volatile("cp.async.wait_group %0;\n" :: "n"(NN));
}

// -------------------- vpm GEMM + overlapped aux work -----------------------
// Blocks with blockIdx.y < VPM_GY: 128x64 GEMM (vpm = vmean @ WvT^T + bv).
// Blocks with blockIdx.y >= VPM_GY: aux — WoT transpose, weight fold, bias.
__global__ void __launch_bounds__(256, 2)
vpm_plus_aux(const __half* __restrict__ Ag,     // vm16
             const __half* __restrict__ Bg,     // WvT
             const float* __restrict__ bias,    // bv
             __half* __restrict__ Cout,         // vpm_h
             const float* __restrict__ Wo,
             const float* __restrict__ Wq,
             const float* __restrict__ bq,
             const float* __restrict__ Woff,
             const float* __restrict__ boff,
             const float* __restrict__ Wattn,
             const float* __restrict__ battn) {
    constexpr int K = Cc, BM = 128, BN = 64, BK = 32;
    constexpr int NK = K / BK;     // 8
    constexpr int STB = 12288;
    __shared__ __align__(128) uint8_t smem[3 * STB];

    const int t = threadIdx.x;

    if (blockIdx.y >= VPM_GY) {
        // ---------------- aux path ----------------
        const int WT  = Cc * Cc;               // 65536  WoT transpose
        const int FT4 = NF * Cc * 4;           // 131072 fold (4-way split)
        const int BT  = NF * 32;               // 4096   bias (warp/output)
        int aid = (((int)blockIdx.y - VPM_GY) * (int)gridDim.x +
                   (int)blockIdx.x) * 256 + t;
        if (aid < WT) {
            int n = aid / Cc, k = aid % Cc;
            g_WoT[aid] = __float2half_rn(Wo[k * Cc + n]);
        } else if (aid < WT + FT4) {
            int local = aid - WT;
            int pair = local >> 2, part = local & 3;
            int k = pair / NF, c = pair % NF;
            float s = 0.f;
            if (c < 96) {
                const float* wq = Wq + k * Cc;
                if (c < 64) {
#pragma unroll 8
                    for (int i = 0; i < 64; i++) {
                        int j = part + 4 * i;
                        s = fmaf(wq[j], Woff[j * 64 + c], s);
                    }
                } else {
                    int cc2 = c - 64;
#pragma unroll 8
                    for (int i = 0; i < 64; i++) {
                        int j = part + 4 * i;
                        s = fmaf(wq[j], Wattn[j * 32 + cc2], s);
                    }
                }
            }
            s += __shfl_xor_sync(0xffffffffu, s, 1);
            s += __shfl_xor_sync(0xffffffffu, s, 2);
            if (part == 0) g_WfT[c * Cc + k] = __float2half_rn(s);
        } else if (aid < WT + FT4 + BT) {
            int local = aid - WT - FT4;
            int o = local >> 5, lane = local & 31;
            float s = 0.f;
            if (o < 64) {
#pragma unroll
                for (int i = 0; i < 8; i++) {
                    int j = lane + 32 * i;
                    s = fmaf(bq[j], Woff[j * 64 + o], s);
                }
            } else if (o < 96) {
                int oo = o - 64;
#pragma unroll
                for (int i = 0; i < 8; i++) {
                    int j = lane + 32 * i;
                    s = fmaf(bq[j], Wattn[j * 32 + oo], s);
                }
            }
#pragma unroll
            for (int off = 16; off > 0; off >>= 1)
                s += __shfl_xor_sync(0xffffffffu, s, off);
            if (lane == 0) {
                float base = (o < 64) ? boff[o] : (o < 96 ? battn[o - 64] : 0.f);
                g_bfold[o] = (o < 96) ? (base + s) : 0.f;
            }
        }
        return;
    }

    // ---------------- vpm GEMM path ----------------
    const uint32_t sb = (uint32_t)__cvta_generic_to_shared(smem);
    const int w = t >> 5, l = t & 31;
    const int wm = w & 3, wn = w >> 2;
    const int g = l >> 2, qq = l & 3;
    const int blockRow = blockIdx.y * BM;
    const int blockCol = blockIdx.x * BN;
    const int lr = t >> 2, lc = t & 3;

    float acc[2][4][4];
#pragma unroll
    for (int i = 0; i < 2; i++)
#pragma unroll
        for (int j = 0; j < 4; j++)
#pragma unroll
            for (int x = 0; x < 4; x++) acc[i][j][x] = 0.f;

    auto stage = [&](int buf, int k0) {
        const uint32_t base = sb + buf * STB;
#pragma unroll
        for (int j = 0; j < 2; j++) {
            int row = lr + j * 64;
            uint32_t sw = (uint32_t)row * 64 + (uint32_t)((lc ^ ((row >> 1) & 3)) * 16);
            cp_async16(base + sw, Ag + (size_t)(blockRow + row) * K + k0 + lc * 8);
        }
        {
            uint32_t sw = (uint32_t)lr * 64 + (uint32_t)((lc ^ ((lr >> 1) & 3)) * 16);
            cp_async16(base + 8192 + sw, Bg + (size_t)(blockCol + lr) * K + k0 + lc * 8);
        }
        cp_commit();
    };

    auto compute = [&](int buf) {
        const uint32_t base = sb + buf * STB;
        const int seg = l >> 3, sl = l & 7;
#pragma unroll
        for (int ks = 0; ks < 2; ks++) {
            uint32_t bF[4][2];
#pragma unroll
            for (int nt = 0; nt < 2; nt++) {
                int r = wn * 32 + nt * 16 + (seg >> 1) * 8 + sl;
                int c = ks * 2 + (seg & 1);
                uint32_t addr = (uint32_t)r * 64 + (uint32_t)((c ^ ((r >> 1) & 3)) * 16);
                uint32_t tmp[4];
                ldmx4(tmp, base + 8192 + addr);
                bF[nt * 2][0] = tmp[0]; bF[nt * 2][1] = tmp[1];
                bF[nt * 2 + 1][0] = tmp[2]; bF[nt * 2 + 1][1] = tmp[3];
            }
            uint32_t aF[2][4];
#pragma unroll
            for (int mt = 0; mt < 2; mt++) {
                int r = wm * 32 + mt * 16 + (seg & 1) * 8 + sl;
                int c = ks * 2 + (seg >> 1);
                uint32_t addr = (uint32_t)r * 64 + (uint32_t)((c ^ ((r >> 1) & 3)) * 16);
                ldmx4(aF[mt], base + addr);
            }
#pragma unroll
            for (int mt = 0; mt < 2; mt++)
#pragma unroll
                for (int nf = 0; nf < 4; nf++)
                    mma_f16(acc[mt][nf], aF[mt], bF[nf]);
        }
    };

    stage(0, 0);
    stage(1, BK);
    for (int kt = 0; kt < NK; kt++) {
        if (kt + 2 < NK) cp_wait<1>();
        else             cp_wait<0>();
        __syncthreads();
        if (kt + 2 < NK) stage((kt + 2) % 3, (kt + 2) * BK);
        compute(kt % 3);
    }

#pragma unroll
    for (int mt = 0; mt < 2; mt++) {
        int row = blockRow + wm * 32 + mt * 16 + g;
#pragma unroll
        for (int nf = 0; nf < 4; nf++) {
            int col = blockCol + wn * 32 + nf * 8 + 2 * qq;
            float2 bb = *(const float2*)&bias[col];
            __half2* Ch = (__half2*)Cout;
            Ch[((size_t)row * Cc + col) >> 1] =
                __floats2half2_rn(acc[mt][nf][0] + bb.x, acc[mt][nf][1] + bb.y);
            Ch[((size_t)(row + 8) * Cc + col) >> 1] =
                __floats2half2_rn(acc[mt][nf][2] + bb.x, acc[mt][nf][3] + bb.y);
        }
    }
}

// -------------------- mega: q convert + offattn GEMM + sampling + out GEMM -
// (identical to R14 passing version)
__global__ void __launch_bounds__(256, 2)
mega_kernel(const float* __restrict__ qg,
            const __half* __restrict__ Bf,
            const float* __restrict__ bfold,
            const __half* __restrict__ WoT,
            const float* __restrict__ bo,
            float* __restrict__ out) {
    constexpr int K = Cc, BK = 32, NK = 8;
    constexpr uint32_t PRE = 0, SOA = 16384;
    constexpr uint32_t ASTG = 16384, ASTG_SZ = 8192;
    constexpr uint32_t CS0 = 32768, CS1 = 16384;
    __shared__ __align__(128) uint8_t smem[49152];
    const uint32_t sb = (uint32_t)__cvta_generic_to_shared(smem);
    float* s_oa = (float*)(smem + SOA);

    const int t = threadIdx.x, w = t >> 5, l = t & 31;
    const int wm = w & 1, wn = w >> 1;
    const int g = l >> 2, qq = l & 3;
    const int seg = l >> 3, sl = l & 7;
    const int blockRow = blockIdx.x * 32;

    // q preload: 32x256 fp32 -> fp16 into PRE (swizzled chunks)
    {
        const int row = t >> 3;
        const int g0 = t & 7;
#pragma unroll
        for (int j = 0; j < 4; j++) {
            int grp = g0 + j * 8;
            int col = grp * 8;
            const float* src = qg + (size_t)(blockRow + row) * K + col;
            float4 a = *(const float4*)src;
            float4 b = *(const float4*)(src + 4);
            __half2 h2[4];
            h2[0] = __floats2half2_rn(a.x, a.y);
            h2[1] = __floats2half2_rn(a.z, a.w);
            h2[2] = __floats2half2_rn(b.x, b.y);
            h2[3] = __floats2half2_rn(b.z, b.w);
            int kt = col >> 5;
            int c16 = (col & 31) >> 3;
            uint32_t addr = PRE + (uint32_t)kt * 2048 + (uint32_t)row * 64 +
                            (uint32_t)((c16 ^ ((row >> 1) & 3)) << 4);
            *(uint4*)(smem + addr) = *(const uint4*)h2;
        }
    }

    // Phase A: offattn GEMM (32 x 128)
    {
        float acc[4][4];
#pragma unroll
        for (int j = 0; j < 4; j++)
#pragma unroll
            for (int x = 0; x < 4; x++) acc[j][x] = 0.f;

        auto stageA = [&](int buf, int k0) {
            const uint32_t base = sb + ASTG + buf * ASTG_SZ;
#pragma unroll
            for (int j = 0; j < 2; j++) {
                int ch = t + j * 256;
                int row = ch >> 2, lc = ch & 3;
                uint32_t sw = (uint32_t)row * 64 + (uint32_t)((lc ^ ((row >> 1) & 3)) * 16);
                cp_async16(base + sw, Bf + (size_t)row * K + k0 + lc * 8);
            }
            cp_commit();
        };

        auto computeA = [&](int buf, int kt) {
            const uint32_t base = sb + ASTG + buf * ASTG_SZ;
#pragma unroll
            for (int ks = 0; ks < 2; ks++) {
                uint32_t bF[4][2];
#pragma unroll
                for (int nt = 0; nt < 2; nt++) {
                    int r = wn * 32 + nt * 16 + (seg >> 1) * 8 + sl;
                    int c = ks * 2 + (seg & 1);
                    uint32_t addr = (uint32_t)r * 64 + (uint32_t)((c ^ ((r >> 1) & 3)) * 16);
                    uint32_t tmp[4];
                    ldmx4(tmp, base + addr);
                    bF[nt * 2][0] = tmp[0]; bF[nt * 2][1] = tmp[1];
                    bF[nt * 2 + 1][0] = tmp[2]; bF[nt * 2 + 1][1] = tmp[3];
                }
                uint32_t aF[4];
                int r = wm * 16 + (seg & 1) * 8 + sl;
                int c = ks * 2 + (seg >> 1);
                uint32_t addr = PRE + (uint32_t)kt * 2048 + (uint32_t)r * 64 +
                                (uint32_t)((c ^ ((r >> 1) & 3)) * 16);
                ldmx4(aF, sb + addr);
#pragma unroll
                for (int nf = 0; nf < 4; nf++)
                    mma_f16(acc[nf], aF, bF[nf]);
            }
        };

        stageA(0, 0);
        stageA(1, BK);
        for (int kt = 0; kt < NK; kt++) {
            if (kt + 2 < NK) cp_wait<1>();
            else             cp_wait<0>();
            __syncthreads();
            if (kt + 2 < NK) stageA((kt + 2) % 3, (kt + 2) * BK);
            computeA(kt % 3, kt);
        }
        __syncthreads();

        int rl = wm * 16 + g;
#pragma unroll
        for (int nf = 0; nf < 4; nf++) {
            int col = wn * 32 + nf * 8 + 2 * qq;
            if (col < 96) {
                float b0 = bfold[col], b1 = bfold[col + 1];
                s_oa[rl * 96 + col]           = acc[nf][0] + b0;
                s_oa[rl * 96 + col + 1]       = acc[nf][1] + b1;
                s_oa[(rl + 8) * 96 + col]     = acc[nf][2] + b0;
                s_oa[(rl + 8) * 96 + col + 1] = acc[nf][3] + b1;
            }
        }
        __syncthreads();
    }

    // pre-issue out-GEMM stage 0 — overlaps sampling
    {
#pragma unroll
        for (int j = 0; j < 4; j++) {
            int ch = t + j * 256;
            int row = ch >> 2, lc = ch & 3;
            uint32_t sw = (uint32_t)row * 64 + (uint32_t)((lc ^ ((row >> 1) & 3)) * 16);
            cp_async16(sb + CS0 + sw, WoT + (size_t)row * K + lc * 8);
        }
        cp_commit();
    }

    // Phase B: softmax + bilinear sampling -> PRE
    for (int rl = w * 4; rl < w * 4 + 4; rl++) {
        const int row = blockRow + rl;
        const int n = row & (Nn - 1);
        const float refx = (float)(n & (GW - 1)) * (1.0f / 63.0f);
        const float refy = (float)(n >> 6) * (1.0f / 63.0f);
        const float* oa = s_oa + rl * 96;

#pragma unroll
        for (int h = 0; h < NHh; h++) {
            float l0 = oa[64 + h * 4 + 0];
            float l1 = oa[64 + h * 4 + 1];
            float l2 = oa[64 + h * 4 + 2];
            float l3 = oa[64 + h * 4 + 3];
            float m  = fmaxf(fmaxf(l0, l1), fmaxf(l2, l3));
            float e0 = __expf(l0 - m), e1 = __expf(l1 - m);
            float e2 = __expf(l2 - m), e3 = __expf(l3 - m);
            float inv = 1.0f / (e0 + e1 + e2 + e3);
            float wp[4] = {e0 * inv, e1 * inv, e2 * inv, e3 * inv};

            const __half* fmap = g_vpm_h + h * HDd + l;
            float acc2 = 0.f;
#pragma unroll
            for (int p = 0; p < NPp; p++) {
                float ox = oa[h * 8 + p * 2 + 0];
                float oy = oa[h * 8 + p * 2 + 1];
                float lx = fminf(fmaxf(refx + ox, 0.f), 1.f);
                float ly = fminf(fmaxf(refy + oy, 0.f), 1.f);
                float x = lx * (float)GW - 0.5f;
                float y = ly * (float)GW - 0.5f;
                float xf = floorf(x), yf = floorf(y);
                float tx = x - xf, ty = y - yf;
                int x0 = (int)xf, y0 = (int)yf;
                int x1 = x0 + 1, y1 = y0 + 1;
                bool vx0 = (x0 >= 0), vx1 = (x1 < GW);
                bool vy0 = (y0 >= 0), vy1 = (y1 < GW);
                float w00 = (1.f - tx) * (1.f - ty);
                float w01 = tx * (1.f - ty);
                float w10 = (1.f - tx) * ty;
                float w11 = tx * ty;
                float a = 0.f;
                if (vx0 && vy0) a = fmaf(w00, __half2float(fmap[(size_t)(y0 * GW + x0) * Cc]), a);
                if (vx1 && vy0) a = fmaf(w01, __half2float(fmap[(size_t)(y0 * GW + x1) * Cc]), a);
                if (vx0 && vy1) a = fmaf(w10, __half2float(fmap[(size_t)(y1 * GW + x0) * Cc]), a);
                if (vx1 && vy1) a = fmaf(w11, __half2float(fmap[(size_t)(y1 * GW + x1) * Cc]), a);
                acc2 = fmaf(wp[p], a, acc2);
            }
            uint32_t boff2 = PRE + (uint32_t)h * 2048 + (uint32_t)rl * 64 +
                             ((((uint32_t)l >> 3) ^ ((uint32_t)(rl >> 1) & 3)) << 4) +
                             ((uint32_t)(l & 7)) * 2;
            *(__half*)(smem + boff2) = __float2half_rn(acc2);
        }
    }
    __syncthreads();

    // Phase C: out GEMM (32 x 256) + bo
    {
        float acc[8][4];
#pragma unroll
        for (int j = 0; j < 8; j++)
#pragma unroll
            for (int x = 0; x < 4; x++) acc[j][x] = 0.f;

        auto stageC = [&](int buf, int k0) {
            const uint32_t base = sb + (buf ? CS1 : CS0);
#pragma unroll
            for (int j = 0; j < 4; j++) {
                int ch = t + j * 256;
                int row = ch >> 2, lc = ch & 3;
                uint32_t sw = (uint32_t)row * 64 + (uint32_t)((lc ^ ((row >> 1) & 3)) * 16);
                cp_async16(base + sw, WoT + (size_t)row * K + k0 + lc * 8);
            }
            cp_commit();
        };

        for (int kt = 0; kt < NK; kt++) {
            cp_wait<0>();
            __syncthreads();
            if (kt + 1 < NK) stageC((kt + 1) & 1, (kt + 1) * BK);
            const uint32_t base = sb + ((kt & 1) ? CS1 : CS0);
#pragma unroll
            for (int ks = 0; ks < 2; ks++) {
                uint32_t bF[8][2];
#pragma unroll
                for (int nt = 0; nt < 4; nt++) {
                    int r = wn * 64 + nt * 16 + (seg >> 1) * 8 + sl;
                    int c = ks * 2 + (seg & 1);
                    uint32_t addr = (uint32_t)r * 64 + (uint32_t)((c ^ ((r >> 1) & 3)) * 16);
                    uint32_t tmp[4];
                    ldmx4(tmp, base + addr);
                    bF[nt * 2][0] = tmp[0]; bF[nt * 2][1] = tmp[1];
                    bF[nt * 2 + 1][0] = tmp[2]; bF[nt * 2 + 1][1] = tmp[3];
                }
                uint32_t aF[4];
                int r = wm * 16 + (seg & 1) * 8 + sl;
                int c = ks * 2 + (seg >> 1);
                uint32_t addr = PRE + (uint32_t)kt * 2048 + (uint32_t)r * 64 +
                                (uint32_t)((c ^ ((r >> 1) & 3)) * 16);
                ldmx4(aF, sb + addr);
#pragma unroll
                for (int nf = 0; nf < 8; nf++)
                    mma_f16(acc[nf], aF, bF[nf]);
            }
        }

        int row = blockRow + wm * 16 + g;
#pragma unroll
        for (int nf = 0; nf < 8; nf++) {
            int col = wn * 64 + nf * 8 + 2 * qq;
            float2 bb = *(const float2*)&bo[col];
            *(float2*)&out[(size_t)row * Cc + col] =
                make_float2(acc[nf][0] + bb.x, acc[nf][1] + bb.y);
            *(float2*)&out[(size_t)(row + 8) * Cc + col] =
                make_float2(acc[nf][2] + bb.x, acc[nf][3] + bb.y);
        }
    }
}

// -------------------- prep: vmean + WvT only (vpm critical path) -----------
__global__ void prep_kernel(const float* __restrict__ v,
                            const float* __restrict__ Wv) {
    const int VT = Nn * Cc / 4;            // 262144
    const int WT = Cc * Cc;                // 65536
    int idx = blockIdx.x * blockDim.x + threadIdx.x;
    if (idx < VT) {
        const float4* v4 = reinterpret_cast<const float4*>(v);
        float4 a = v4[idx], b = v4[idx + VT], c = v4[idx + 2 * VT], d = v4[idx + 3 * VT];
        __half2 h2[2];
        h2[0] = __floats2half2_rn(0.25f * (a.x + b.x + c.x + d.x),
                                  0.25f * (a.y + b.y + c.y + d.y));
        h2[1] = __floats2half2_rn(0.25f * (a.z + b.z + c.z + d.z),
                                  0.25f * (a.w + b.w + c.w + d.w));
        *(uint2*)&g_vm16[idx * 4] = *(const uint2*)h2;
    } else if (idx < VT + WT) {
        int li = idx - VT;
        int n = li / Cc, k = li % Cc;
        g_WvT[li] = __float2half_rn(Wv[k * Cc + n]);
    }
}

// ---------------------------------------------------------------------------
extern "C" void kernel_launch(void* const* d_in, const int* in_sizes, int n_in,
                              void* d_out, int out_size) {
    (void)in_sizes; (void)n_in; (void)out_size;
    const float* q     = (const float*)d_in[0];
    const float* v     = (const float*)d_in[2];
    const float* Wq    = (const float*)d_in[3];
    const float* bq    = (const float*)d_in[4];
    const float* Wv    = (const float*)d_in[7];
    const float* bv    = (const float*)d_in[8];
    const float* Wo    = (const float*)d_in[9];
    const float* bo    = (const float*)d_in[10];
    const float* Woff  = (const float*)d_in[11];
    const float* boff  = (const float*)d_in[12];
    const float* Wattn = (const float*)d_in[13];
    const float* battn = (const float*)d_in[14];
    float* out = (float*)d_out;

    float* p_bfold;
    __half *p_vm16, *p_vpmh, *p_WvT, *p_WoT, *p_WfT;
    cudaGetSymbolAddress((void**)&p_vm16,  g_vm16);
    cudaGetSymbolAddress((void**)&p_vpmh,  g_vpm_h);
    cudaGetSymbolAddress((void**)&p_bfold, g_bfold);
    cudaGetSymbolAddress((void**)&p_WvT,   g_WvT);
    cudaGetSymbolAddress((void**)&p_WoT,   g_WoT);
    cudaGetSymbolAddress((void**)&p_WfT,   g_WfT);

    // 1. prep: vmean + WvT (vpm inputs only)
    {
        int tot = Nn * Cc / 4 + Cc * Cc;
        prep_kernel<<<(tot + 255) / 256, 256>>>(v, Wv);
    }

    // 2. vpm GEMM (y<32) + aux fold/transpose/bias blocks (y>=32)
    {
        // aux needs 65536 + 131072 + 4096 = 200704 threads = 784 blocks
        // gridDim.x = 4 -> 196 extra y rows
        dim3 grid(Cc / 64, VPM_GY + 196);
        vpm_plus_aux<<<grid, 256>>>(p_vm16, p_WvT, bv, p_vpmh,
                                    Wo, Wq, bq, Woff, boff, Wattn, battn);
    }

    // 3. mega: q convert + offattn GEMM + sampling + out GEMM
    mega_kernel<<<ROWS / 32, 256>>>(q, p_WfT, p_bfold, p_WoT, bo, out);
}